// round 1
// baseline (speedup 1.0000x reference)
#include <cuda_runtime.h>
#include <cstdint>

#define CIN 256
#define HWSZ 784
#define DD 64
#define NP 200
#define NCLS 10
#define NIMG 256
#define TPB 256
#define NCHUNK 784            // 200704 / 256 exactly

typedef unsigned long long u64;

__device__ __forceinline__ u64 pack2(float lo, float hi) {
    u64 r; asm("mov.b64 %0, {%1, %2};" : "=l"(r) : "f"(lo), "f"(hi)); return r;
}
__device__ __forceinline__ void unpack2(u64 v, float& lo, float& hi) {
    asm("mov.b64 {%0, %1}, %2;" : "=f"(lo), "=f"(hi) : "l"(v));
}
__device__ __forceinline__ void fma2(u64& d, u64 a, u64 b) {
    asm("fma.rn.f32x2 %0, %1, %2, %0;" : "+l"(d) : "l"(a), "l"(b));
}
__device__ __forceinline__ u64 add2(u64 a, u64 b) {
    u64 r; asm("add.rn.f32x2 %0, %1, %2;" : "=l"(r) : "l"(a), "l"(b)); return r;
}

// smem layout (floats)
#define OFF_W1   0
#define OFF_W2   (OFF_W1 + DD*CIN)       // 16384
#define OFF_PR   (OFF_W2 + DD*DD)        // +4096
#define OFF_P2   (OFF_PR + NP*DD)        // +12800
#define OFF_B1   (OFF_P2 + 208)
#define OFF_B2   (OFF_B1 + 64)
#define OFF_HB   (OFF_B2 + 64)           // hbuf [64][256]
#define SMEM_FLOATS (OFF_HB + DD*TPB)
#define SMEM_BYTES  (SMEM_FLOATS * 4)    // 200000 B

__global__ __launch_bounds__(TPB, 1)
void proto_main(const float* __restrict__ x, const float* __restrict__ W1,
                const float* __restrict__ b1, const float* __restrict__ W2,
                const float* __restrict__ b2, const float* __restrict__ prot,
                unsigned* __restrict__ gmin)
{
    extern __shared__ float sm[];
    float* sW1 = sm + OFF_W1;   // [c][o]
    float* sW2 = sm + OFF_W2;   // [k][o]
    float* sPr = sm + OFF_PR;   // [p][q]
    float* sP2 = sm + OFF_P2;
    float* sB1 = sm + OFF_B1;
    float* sB2 = sm + OFF_B2;
    float* hbuf = sm + OFF_HB;  // [k][tid]

    const int tid = threadIdx.x;

    // Stage weights (transposed reads keep smem writes conflict-free; one-time cost)
    for (int i = tid; i < DD*CIN; i += TPB) {
        int o = i & 63, c = i >> 6;
        sW1[i] = W1[o*CIN + c];
    }
    for (int i = tid; i < DD*DD; i += TPB) {
        int o = i & 63, k = i >> 6;
        sW2[i] = W2[o*DD + k];
    }
    for (int i = tid; i < NP*DD; i += TPB) sPr[i] = prot[i];
    if (tid < DD) { sB1[tid] = b1[tid]; sB2[tid] = b2[tid]; }
    __syncthreads();
    if (tid < NP) {
        float s = 0.f;
        #pragma unroll
        for (int q = 0; q < DD; q++) { float v = sPr[tid*DD + q]; s = fmaf(v, v, s); }
        sP2[tid] = s;
    }
    __syncthreads();

    const int lane = tid & 31;

    for (int chunk = blockIdx.x; chunk < NCHUNK; chunk += gridDim.x) {
        const int g   = chunk * TPB + tid;          // global pixel id, < 200704
        const int n   = g / HWSZ;
        const int pix = g - n * HWSZ;
        const float* xp = x + (size_t)n * (CIN*HWSZ) + pix;

        // ---- stage 1: h = relu(W1 @ x + b1), channel-pair packed f32x2 ----
        u64 acc[32];
        #pragma unroll
        for (int q = 0; q < 32; q++) acc[q] = 0ull;

        for (int c0 = 0; c0 < CIN; c0 += 8) {
            float xv[8];
            #pragma unroll
            for (int j = 0; j < 8; j++) xv[j] = __ldg(xp + (c0 + j) * HWSZ);
            #pragma unroll
            for (int j = 0; j < 8; j++) {
                u64 xq = pack2(xv[j], xv[j]);
                const ulonglong2* wr = (const ulonglong2*)(sW1 + (c0 + j) * DD);
                #pragma unroll
                for (int q = 0; q < 16; q++) {
                    ulonglong2 w = wr[q];           // broadcast LDS.128
                    fma2(acc[2*q],     xq, w.x);
                    fma2(acc[2*q + 1], xq, w.y);
                }
            }
        }
        // bias + relu -> private smem column (dynamic index in stage 2)
        #pragma unroll
        for (int q = 0; q < 32; q++) {
            float a0, a1; unpack2(acc[q], a0, a1);
            a0 = fmaxf(a0 + sB1[2*q], 0.f);
            a1 = fmaxf(a1 + sB1[2*q + 1], 0.f);
            hbuf[(2*q) * TPB + tid]     = a0;
            hbuf[(2*q + 1) * TPB + tid] = a1;
        }

        // ---- stage 2: f = sigmoid(W2 @ h + b2) ----
        u64 facc[32];
        #pragma unroll
        for (int q = 0; q < 32; q++) facc[q] = pack2(sB2[2*q], sB2[2*q + 1]);
        for (int k = 0; k < DD; k++) {
            float hk = hbuf[k * TPB + tid];
            u64 hq = pack2(hk, hk);
            const ulonglong2* wr = (const ulonglong2*)(sW2 + k * DD);
            #pragma unroll
            for (int q = 0; q < 16; q++) {
                ulonglong2 w = wr[q];
                fma2(facc[2*q],     hq, w.x);
                fma2(facc[2*q + 1], hq, w.y);
            }
        }
        // sigmoid + ||f||^2, repack in place
        float sumf2 = 0.f;
        #pragma unroll
        for (int q = 0; q < 32; q++) {
            float v0, v1; unpack2(facc[q], v0, v1);
            float s0 = __fdividef(1.f, 1.f + __expf(-v0));
            float s1 = __fdividef(1.f, 1.f + __expf(-v1));
            sumf2 = fmaf(s0, s0, sumf2);
            sumf2 = fmaf(s1, s1, sumf2);
            facc[q] = pack2(s0, s1);
        }

        // ---- stage 3: distances + spatial min ----
        int nw0  = __shfl_sync(0xffffffffu, n, 0);
        int nw31 = __shfl_sync(0xffffffffu, n, 31);
        bool uni = (nw0 == nw31);                    // warp entirely within one image?
        unsigned* gbase = gmin + (size_t)n * NP;

        for (int p = 0; p < NP; p++) {
            const ulonglong2* pr = (const ulonglong2*)(sPr + p * DD);
            u64 d0 = 0ull, d1 = 0ull, d2 = 0ull, d3 = 0ull;
            #pragma unroll
            for (int q = 0; q < 8; q++) {
                ulonglong2 wA = pr[2*q];
                ulonglong2 wB = pr[2*q + 1];
                fma2(d0, facc[4*q],     wA.x);
                fma2(d1, facc[4*q + 1], wA.y);
                fma2(d2, facc[4*q + 2], wB.x);
                fma2(d3, facc[4*q + 3], wB.y);
            }
            u64 ds = add2(add2(d0, d1), add2(d2, d3));
            float s0, s1; unpack2(ds, s0, s1);
            float dot  = s0 + s1;
            float dist = fmaxf(fmaf(-2.f, dot, sumf2 + sP2[p]), 0.f);
            if (uni) {
                float m = dist;
                #pragma unroll
                for (int sh = 16; sh > 0; sh >>= 1)
                    m = fminf(m, __shfl_xor_sync(0xffffffffu, m, sh));
                if (lane == 0) atomicMin(gbase + p, __float_as_uint(m));
            } else {
                // rare: warp straddles an image boundary (<= 1 warp per chunk)
                atomicMin(gbase + p, __float_as_uint(dist));
            }
        }
    }
}

__global__ void init_min(unsigned* __restrict__ gmin) {
    int i = blockIdx.x * blockDim.x + threadIdx.x;
    if (i < NIMG * NP) gmin[i] = 0x7F800000u;   // +inf
}

__global__ void logits_k(const float* __restrict__ md, const float* __restrict__ lw,
                         const float* __restrict__ lb, float* __restrict__ out) {
    int n    = blockIdx.x;
    int cls  = threadIdx.x >> 5;     // 10 warps per block
    int lane = threadIdx.x & 31;
    if (cls >= NCLS) return;
    float s = 0.f;
    for (int p = lane; p < NP; p += 32)
        s = fmaf(-md[n * NP + p], lw[cls * NP + p], s);
    #pragma unroll
    for (int sh = 16; sh > 0; sh >>= 1)
        s += __shfl_xor_sync(0xffffffffu, s, sh);
    if (lane == 0) out[n * NCLS + cls] = s + lb[cls];
}

extern "C" void kernel_launch(void* const* d_in, const int* in_sizes, int n_in,
                              void* d_out, int out_size)
{
    const float* x    = (const float*)d_in[0];
    const float* W1   = (const float*)d_in[1];
    const float* b1   = (const float*)d_in[2];
    const float* W2   = (const float*)d_in[3];
    const float* b2   = (const float*)d_in[4];
    const float* prot = (const float*)d_in[5];
    const float* lw   = (const float*)d_in[6];
    const float* lb   = (const float*)d_in[7];

    float* out      = (float*)d_out;
    float* logits   = out;                          // [256, 10]
    unsigned* gmin  = (unsigned*)(out + NIMG*NCLS); // [256, 200] as float bits

    cudaFuncSetAttribute(proto_main, cudaFuncAttributeMaxDynamicSharedMemorySize, SMEM_BYTES);
    int sms = 148;
    cudaDeviceGetAttribute(&sms, cudaDevAttrMultiProcessorCount, 0);

    init_min<<<(NIMG*NP + 255) / 256, 256>>>(gmin);
    proto_main<<<sms, TPB, SMEM_BYTES>>>(x, W1, b1, W2, b2, prot, gmin);
    logits_k<<<NIMG, NCLS * 32>>>((const float*)gmin, lw, lb, logits);
}

// round 2
// speedup vs baseline: 1.0046x; 1.0046x over previous
#include <cuda_runtime.h>
#include <cstdint>

#define CIN   256
#define HWSZ  784
#define DD    64
#define NP    200
#define NPPAD 224
#define NCLS  10
#define NIMG  256
#define TPB   256
#define NCHUNK 784            // 200704 / 256 exactly
#define FULL  0xffffffffu

typedef unsigned long long u64;

__device__ __forceinline__ u64 pack2(float lo, float hi) {
    u64 r; asm("mov.b64 %0, {%1, %2};" : "=l"(r) : "f"(lo), "f"(hi)); return r;
}
__device__ __forceinline__ void unpack2(u64 v, float& lo, float& hi) {
    asm("mov.b64 {%0, %1}, %2;" : "=f"(lo), "=f"(hi) : "l"(v));
}
__device__ __forceinline__ void fma2(u64& d, u64 a, u64 b) {
    asm("fma.rn.f32x2 %0, %1, %2, %0;" : "+l"(d) : "l"(a), "l"(b));
}
__device__ __forceinline__ u64 add2(u64 a, u64 b) {
    u64 r; asm("add.rn.f32x2 %0, %1, %2;" : "=l"(r) : "l"(a), "l"(b)); return r;
}

// smem layout (bytes)
#define OFF_W1   0                         // 16384 f  = 65536 B  [c][2l]=(W1[l][c],W1[l+32][c])
#define OFF_W2   65536                     // 4096 f   = 16384 B  [k][2l]=(W2[l][k],W2[l+32][k])
#define OFF_PRD  81920                     // 64*224 u64 = 114688 B  dup pairs of -2*prot[p][c]
#define OFF_P2D  196608                    // 224 u64 = 1792 B
#define OFF_B1   198400                    // 64 f
#define OFF_B2   198656                    // 64 f
#define OFF_S2   198912                    // 8 warps * 16 u64 = 1024 B
#define SMEM_BYTES 199936

__device__ __forceinline__ void s1_step(const float* __restrict__ sW1i, int c, int lane,
                                        float xlo, float xhi, int srcBase,
                                        u64* accA, u64* accB) {
    float2 w = *(const float2*)(sW1i + c * 64 + 2 * lane);
    u64 wA = pack2(w.x, w.x), wB = pack2(w.y, w.y);
    #pragma unroll
    for (int jj = 0; jj < 16; jj++) {
        float a = __shfl_sync(FULL, xlo, jj + srcBase);
        float b = __shfl_sync(FULL, xhi, jj + srcBase);
        u64 xq = pack2(a, b);
        fma2(accA[jj], xq, wA);
        fma2(accB[jj], xq, wB);
    }
}

__device__ __forceinline__ void s2_step(const float* __restrict__ sW2i, int krow, int lane, int src,
                                        const float* hlo, const float* hhi,
                                        u64* fAacc, u64* fBacc) {
    float2 w = *(const float2*)(sW2i + krow * 64 + 2 * lane);
    u64 wA = pack2(w.x, w.x), wB = pack2(w.y, w.y);
    #pragma unroll
    for (int jj = 0; jj < 16; jj++) {
        float a = __shfl_sync(FULL, hlo[jj], src);
        float b = __shfl_sync(FULL, hhi[jj], src);
        u64 hq = pack2(a, b);
        fma2(fAacc[jj], hq, wA);
        fma2(fBacc[jj], hq, wB);
    }
}

__global__ __launch_bounds__(TPB, 1)
void proto_main(const float* __restrict__ x, const float* __restrict__ W1,
                const float* __restrict__ b1, const float* __restrict__ W2,
                const float* __restrict__ b2, const float* __restrict__ prot,
                unsigned* __restrict__ gmin)
{
    extern __shared__ char sm8[];
    float* sW1i = (float*)(sm8 + OFF_W1);
    float* sW2i = (float*)(sm8 + OFF_W2);
    u64*   sPrD = (u64*)(sm8 + OFF_PRD);
    u64*   sP2d = (u64*)(sm8 + OFF_P2D);
    float* sB1  = (float*)(sm8 + OFF_B1);
    float* sB2  = (float*)(sm8 + OFF_B2);
    u64*   s2buf = (u64*)(sm8 + OFF_S2);

    const int tid = threadIdx.x;

    // ---- stage weights (one-time) ----
    for (int i = tid; i < DD * CIN; i += TPB) {            // interleaved W1
        int c = i >> 6, t = i & 63, l = t >> 1, h = t & 1;
        sW1i[i] = W1[(l + h * 32) * CIN + c];
    }
    for (int i = tid; i < DD * DD; i += TPB) {             // interleaved W2
        int k = i >> 6, t = i & 63, l = t >> 1, h = t & 1;
        sW2i[i] = W2[(l + h * 32) * DD + k];
    }
    for (int i = tid; i < DD * NPPAD; i += TPB) {          // duplicated -2*prototypes, [c][p]
        int c = i / NPPAD, p = i - c * NPPAD;
        float w = (p < NP) ? (-2.0f * prot[p * DD + c]) : 0.0f;
        sPrD[i] = pack2(w, w);
    }
    if (tid < NPPAD) {
        float s = 0.0f;
        if (tid < NP) {
            #pragma unroll
            for (int c = 0; c < DD; c++) { float v = prot[tid * DD + c]; s = fmaf(v, v, s); }
        }
        sP2d[tid] = pack2(s, s);
    }
    if (tid < DD) { sB1[tid] = b1[tid]; sB2[tid] = b2[tid]; }
    __syncthreads();

    const int wid  = tid >> 5;
    const int lane = tid & 31;
    const int jj_l = lane & 15;
    const int chf  = lane >> 4;

    for (int chunk = blockIdx.x; chunk < NCHUNK; chunk += gridDim.x) {
        const int warpPix = chunk * TPB + wid * 32;
        const int nA  = warpPix / HWSZ;
        const int bnd = (nA + 1) * HWSZ;
        const bool span = (warpPix + 31) >= bnd;

        // lane's fixed pixel pair (pairs never straddle images: HWSZ even)
        const int p0l = warpPix + 2 * jj_l;
        const int nl  = p0l / HWSZ;
        const float* xl = x + (size_t)nl * (CIN * HWSZ) + (p0l - nl * HWSZ);

        // ---- stage 1: h = relu(W1 x + b1); lane owns ch {l, l+32}, 16 pixel-pairs ----
        u64 accA[16], accB[16];
        {
            float bA = sB1[lane], bB = sB1[lane + 32];
            u64 iA = pack2(bA, bA), iB = pack2(bB, bB);
            #pragma unroll
            for (int jj = 0; jj < 16; jj++) { accA[jj] = iA; accB[jj] = iB; }
        }
        for (int c0 = 0; c0 < CIN; c0 += 4) {
            float2 x0 = *(const float2*)(xl + (c0 + chf) * HWSZ);
            float2 x1 = *(const float2*)(xl + (c0 + 2 + chf) * HWSZ);
            s1_step(sW1i, c0 + 0, lane, x0.x, x0.y, 0,  accA, accB);
            s1_step(sW1i, c0 + 1, lane, x0.x, x0.y, 16, accA, accB);
            s1_step(sW1i, c0 + 2, lane, x1.x, x1.y, 0,  accA, accB);
            s1_step(sW1i, c0 + 3, lane, x1.x, x1.y, 16, accA, accB);
        }
        float hAlo[16], hAhi[16], hBlo[16], hBhi[16];
        #pragma unroll
        for (int jj = 0; jj < 16; jj++) {
            float a, b;
            unpack2(accA[jj], a, b); hAlo[jj] = fmaxf(a, 0.f); hAhi[jj] = fmaxf(b, 0.f);
            unpack2(accB[jj], a, b); hBlo[jj] = fmaxf(a, 0.f); hBhi[jj] = fmaxf(b, 0.f);
        }

        // ---- stage 2: f = sigmoid(W2 h + b2) ----
        u64 fAacc[16], fBacc[16];
        {
            float bA = sB2[lane], bB = sB2[lane + 32];
            u64 iA = pack2(bA, bA), iB = pack2(bB, bB);
            #pragma unroll
            for (int jj = 0; jj < 16; jj++) { fAacc[jj] = iA; fBacc[jj] = iB; }
        }
        #pragma unroll 1
        for (int k = 0; k < 32; k++) s2_step(sW2i, k,      lane, k, hAlo, hAhi, fAacc, fBacc);
        #pragma unroll 1
        for (int k = 0; k < 32; k++) s2_step(sW2i, k + 32, lane, k, hBlo, hBhi, fAacc, fBacc);

        float fAlo[16], fAhi[16], fBlo[16], fBhi[16];
        #pragma unroll
        for (int jj = 0; jj < 16; jj++) {
            float a, b;
            unpack2(fAacc[jj], a, b);
            fAlo[jj] = __fdividef(1.f, 1.f + __expf(-a));
            fAhi[jj] = __fdividef(1.f, 1.f + __expf(-b));
            unpack2(fBacc[jj], a, b);
            fBlo[jj] = __fdividef(1.f, 1.f + __expf(-a));
            fBhi[jj] = __fdividef(1.f, 1.f + __expf(-b));
        }

        // ---- ||f||^2 per pixel: lane partial + butterfly across lanes ----
        float s2lo[16], s2hi[16];
        #pragma unroll
        for (int jj = 0; jj < 16; jj++) {
            s2lo[jj] = fmaf(fAlo[jj], fAlo[jj], fBlo[jj] * fBlo[jj]);
            s2hi[jj] = fmaf(fAhi[jj], fAhi[jj], fBhi[jj] * fBhi[jj]);
        }
        #pragma unroll
        for (int d = 16; d > 0; d >>= 1) {
            #pragma unroll
            for (int jj = 0; jj < 16; jj++) {
                s2lo[jj] += __shfl_xor_sync(FULL, s2lo[jj], d);
                s2hi[jj] += __shfl_xor_sync(FULL, s2hi[jj], d);
            }
        }
        if (lane == 0) {
            #pragma unroll
            for (int jj = 0; jj < 16; jj++) s2buf[wid * 16 + jj] = pack2(s2lo[jj], s2hi[jj]);
        }
        __syncwarp();

        // ---- stage 3: distances + spatial min; lane owns protos {lane+32m} ----
        u64 p2r[7];
        #pragma unroll
        for (int m = 0; m < 7; m++) p2r[m] = sP2d[lane + 32 * m];
        float minA[7], minB[7];
        #pragma unroll
        for (int m = 0; m < 7; m++) { minA[m] = __int_as_float(0x7f800000); minB[m] = minA[m]; }

        #pragma unroll
        for (int blk = 0; blk < 4; blk++) {
            u64 dot[28];
            #pragma unroll
            for (int i = 0; i < 28; i++) dot[i] = 0ull;

            #pragma unroll 4
            for (int c = 0; c < 32; c++) {
                u64 fc[4];
                #pragma unroll
                for (int j = 0; j < 4; j++) {
                    float a = __shfl_sync(FULL, fAlo[blk * 4 + j], c);
                    float b = __shfl_sync(FULL, fAhi[blk * 4 + j], c);
                    fc[j] = pack2(a, b);
                }
                const u64* wr = sPrD + c * NPPAD + lane;
                #pragma unroll
                for (int m = 0; m < 7; m++) {
                    u64 wm = wr[32 * m];
                    #pragma unroll
                    for (int j = 0; j < 4; j++) fma2(dot[j * 7 + m], fc[j], wm);
                }
            }
            #pragma unroll 4
            for (int c = 0; c < 32; c++) {
                u64 fc[4];
                #pragma unroll
                for (int j = 0; j < 4; j++) {
                    float a = __shfl_sync(FULL, fBlo[blk * 4 + j], c);
                    float b = __shfl_sync(FULL, fBhi[blk * 4 + j], c);
                    fc[j] = pack2(a, b);
                }
                const u64* wr = sPrD + (c + 32) * NPPAD + lane;
                #pragma unroll
                for (int m = 0; m < 7; m++) {
                    u64 wm = wr[32 * m];
                    #pragma unroll
                    for (int j = 0; j < 4; j++) fma2(dot[j * 7 + m], fc[j], wm);
                }
            }
            // epilogue: dist = relu(s2 + dot' + p2), track per-image min
            #pragma unroll
            for (int j = 0; j < 4; j++) {
                u64 s2v = s2buf[wid * 16 + blk * 4 + j];
                bool second = (warpPix + 2 * (blk * 4 + j)) >= bnd;
                #pragma unroll
                for (int m = 0; m < 7; m++) {
                    u64 dv = add2(add2(dot[j * 7 + m], s2v), p2r[m]);
                    float d0, d1; unpack2(dv, d0, d1);
                    d0 = fmaxf(d0, 0.f); d1 = fmaxf(d1, 0.f);
                    float md = fminf(d0, d1);
                    if (second) minB[m] = fminf(minB[m], md);
                    else        minA[m] = fminf(minA[m], md);
                }
            }
        }

        unsigned* gA = gmin + (size_t)nA * NP;
        #pragma unroll
        for (int m = 0; m < 7; m++) {
            int p = lane + 32 * m;
            if (p < NP) {
                atomicMin(gA + p, __float_as_uint(minA[m]));
                if (span) atomicMin(gA + NP + p, __float_as_uint(minB[m]));
            }
        }
        __syncwarp();
    }
}

__global__ void init_min(unsigned* __restrict__ gmin) {
    int i = blockIdx.x * blockDim.x + threadIdx.x;
    if (i < NIMG * NP) gmin[i] = 0x7F800000u;   // +inf
}

__global__ void logits_k(const float* __restrict__ md, const float* __restrict__ lw,
                         const float* __restrict__ lb, float* __restrict__ out) {
    int n    = blockIdx.x;
    int cls  = threadIdx.x >> 5;     // 10 warps per block
    int lane = threadIdx.x & 31;
    if (cls >= NCLS) return;
    float s = 0.f;
    for (int p = lane; p < NP; p += 32)
        s = fmaf(-md[n * NP + p], lw[cls * NP + p], s);
    #pragma unroll
    for (int sh = 16; sh > 0; sh >>= 1)
        s += __shfl_xor_sync(FULL, s, sh);
    if (lane == 0) out[n * NCLS + cls] = s + lb[cls];
}

extern "C" void kernel_launch(void* const* d_in, const int* in_sizes, int n_in,
                              void* d_out, int out_size)
{
    const float* x    = (const float*)d_in[0];
    const float* W1   = (const float*)d_in[1];
    const float* b1   = (const float*)d_in[2];
    const float* W2   = (const float*)d_in[3];
    const float* b2   = (const float*)d_in[4];
    const float* prot = (const float*)d_in[5];
    const float* lw   = (const float*)d_in[6];
    const float* lb   = (const float*)d_in[7];

    float* out      = (float*)d_out;
    float* logits   = out;                          // [256, 10]
    unsigned* gmin  = (unsigned*)(out + NIMG*NCLS); // [256, 200] as float bits

    cudaFuncSetAttribute(proto_main, cudaFuncAttributeMaxDynamicSharedMemorySize, SMEM_BYTES);
    int sms = 148;
    cudaDeviceGetAttribute(&sms, cudaDevAttrMultiProcessorCount, 0);

    init_min<<<(NIMG*NP + 255) / 256, 256>>>(gmin);
    proto_main<<<sms, TPB, SMEM_BYTES>>>(x, W1, b1, W2, b2, prot, gmin);
    logits_k<<<NIMG, NCLS * 32>>>((const float*)gmin, lw, lb, logits);
}

// round 6
// speedup vs baseline: 1.7585x; 1.7505x over previous
#include <cuda_runtime.h>
#include <cuda_bf16.h>
#include <cstdint>

#define NP     200
#define NPP    208          // padded prototypes (26 n-tiles of 8)
#define NCLS   10
#define NIMG   256
#define HWSZ   784
#define CIN    256
#define DD     64
#define MT     128
#define NTILES 1568         // 200704 / 128
#define TPB    256
#define FULL   0xffffffffu

// ---- smem byte offsets ----
#define S_X    0            // [128][256] bf16, 512 B/row          = 65536
#define S_W1   65536        // [64][256] bf16                      = 32768
#define S_H    98304        // [128][64] bf16, 128 B/row           = 16384
#define S_FH   114688       // f hi                                = 16384
#define S_FL   131072       // f lo                                = 16384
#define S_W2   147456       // [64][64] bf16                       = 8192
#define S_PH   155648       // -2*prot hi [208][64]                = 26624
#define S_PL   182272       //                                     = 26624
#define S_P2   208896       // [208] f32
#define S_B1   209728
#define S_B2   209984
#define S_S2   210240       // [128] f32
#define S_WA   210752       // warp mins A [8][208] f32 = 6656
#define S_WB   217408       // warp mins B
#define SMEM_TOTAL 224064

__device__ __forceinline__ uint32_t smem_u32(const void* p) {
    uint32_t a;
    asm("{ .reg .u64 t; cvta.to.shared.u64 t, %1; cvt.u32.u64 %0, t; }" : "=r"(a) : "l"(p));
    return a;
}
__device__ __forceinline__ void ldm4(uint32_t* r, uint32_t addr) {
    asm volatile("ldmatrix.sync.aligned.m8n8.x4.shared.b16 {%0,%1,%2,%3}, [%4];"
        : "=r"(r[0]), "=r"(r[1]), "=r"(r[2]), "=r"(r[3]) : "r"(addr));
}
__device__ __forceinline__ void mma16816(float* c, const uint32_t* a, const uint32_t* b) {
    asm volatile("mma.sync.aligned.m16n8k16.row.col.f32.bf16.bf16.f32 "
        "{%0,%1,%2,%3}, {%4,%5,%6,%7}, {%8,%9}, {%0,%1,%2,%3};"
        : "+f"(c[0]), "+f"(c[1]), "+f"(c[2]), "+f"(c[3])
        : "r"(a[0]), "r"(a[1]), "r"(a[2]), "r"(a[3]), "r"(b[0]), "r"(b[1]));
}
// swizzled byte offset within a row-major tile (ROWB multiple of 128)
__device__ __forceinline__ uint32_t swz(int row, int cb, int rowb) {
    return (uint32_t)(row * rowb) + (uint32_t)(cb ^ ((row & 7) << 4));
}
__device__ __forceinline__ float sigmoidf_(float v) {
    return __fdividef(1.f, 1.f + __expf(-v));
}
__device__ __forceinline__ float wmin3(float m) {
    m = fminf(m, __shfl_xor_sync(FULL, m, 4));
    m = fminf(m, __shfl_xor_sync(FULL, m, 8));
    m = fminf(m, __shfl_xor_sync(FULL, m, 16));
    return m;
}

__global__ __launch_bounds__(TPB, 1)
void proto_mma(const float* __restrict__ x, const float* __restrict__ W1,
               const float* __restrict__ b1, const float* __restrict__ W2,
               const float* __restrict__ b2, const float* __restrict__ prot,
               unsigned* __restrict__ gmin)
{
    extern __shared__ char sm8[];
    const uint32_t sb = smem_u32(sm8);
    float* sP2 = (float*)(sm8 + S_P2);
    float* sB1 = (float*)(sm8 + S_B1);
    float* sB2 = (float*)(sm8 + S_B2);
    float* sS2 = (float*)(sm8 + S_S2);
    float* sWA = (float*)(sm8 + S_WA);
    float* sWB = (float*)(sm8 + S_WB);

    const int tid  = threadIdx.x;
    const int w    = tid >> 5;
    const int lane = tid & 31;

    // ---- one-time weight staging (bf16, swizzled) ----
    for (int i = tid; i < DD * CIN; i += TPB) {
        int o = i >> 8, c = i & 255;
        *(__nv_bfloat16*)(sm8 + S_W1 + swz(o, c * 2, 512)) = __float2bfloat16(W1[i]);
    }
    for (int i = tid; i < DD * DD; i += TPB) {
        int o = i >> 6, k = i & 63;
        *(__nv_bfloat16*)(sm8 + S_W2 + swz(o, k * 2, 128)) = __float2bfloat16(W2[i]);
    }
    for (int i = tid; i < NPP * DD; i += TPB) {
        int p = i >> 6, c = i & 63;
        float v = (p < NP) ? (-2.0f * prot[p * DD + c]) : 0.0f;
        __nv_bfloat16 hi = __float2bfloat16(v);
        __nv_bfloat16 lo = __float2bfloat16(v - __bfloat162float(hi));
        uint32_t off = swz(p, c * 2, 128);
        *(__nv_bfloat16*)(sm8 + S_PH + off) = hi;
        *(__nv_bfloat16*)(sm8 + S_PL + off) = lo;
    }
    if (tid < NPP) {
        float s = 0.f;
        if (tid < NP) {
            #pragma unroll
            for (int c = 0; c < DD; c++) { float v = prot[tid * DD + c]; s = fmaf(v, v, s); }
        }
        sP2[tid] = s;
    }
    if (tid < DD) { sB1[tid] = b1[tid]; sB2[tid] = b2[tid]; }
    __syncthreads();

    // ---- per-thread fragment geometry ----
    const int rowA = w * 16 + (lane & 15);          // A ldmatrix row (tile-local pixel)
    const int c16  = lane & 16;                      // A k-half select (bytes)
    const int swA  = (rowA & 7) << 4;
    const int rowB = (lane & 7) | ((lane & 16) >> 1);// B ldmatrix n within 16-group
    const int cB16 = (lane & 8) << 1;                // B k-half select (bytes)
    const int swB  = (rowB & 7) << 4;
    const int r1 = lane >> 2, e = (lane & 3) * 2;    // C fragment rows/cols
    const int gr1 = w * 16 + r1, gr2 = gr1 + 8;
    const int swc = (r1 & 7) << 4;                   // same swizzle for rows r1, r1+8

    const uint32_t aX  = sb + S_X  + rowA * 512;
    const uint32_t aH  = sb + S_H  + rowA * 128;
    const uint32_t aFH = sb + S_FH + rowA * 128;
    const uint32_t aFL = sb + S_FL + rowA * 128;
    const uint32_t bW1 = sb + S_W1 + rowB * 512;
    const uint32_t bW2 = sb + S_W2 + rowB * 128;
    const uint32_t bPH = sb + S_PH + rowB * 128;
    const uint32_t bPL = sb + S_PL + rowB * 128;
    const float INF = __int_as_float(0x7f800000);

    for (int tile = blockIdx.x; tile < NTILES; tile += gridDim.x) {
        const int px0  = tile * MT;
        const int nA   = px0 / HWSZ;
        const int bndg = (nA + 1) * HWSZ;
        const bool hasB = (px0 + MT - 1) >= bndg;
        const int bndw = bndg - px0;                 // rows < bndw belong to image nA

        // ---- transpose-load x -> bf16 smem (warp-private 16 rows) ----
        {
            const int pxl = lane & 15;
            const int half = lane >> 4;
            const int g = px0 + w * 16 + pxl;
            const int n = g / HWSZ;
            const int pix = g - n * HWSZ;
            const float* ptr = x + ((size_t)n * CIN + half) * HWSZ + pix;
            const int row = w * 16 + pxl;
            const uint32_t xb = sb + S_X + row * 512;
            const uint32_t sx = (row & 7) << 4;
            #pragma unroll 4
            for (int it = 0; it < 128; it++) {
                float v = __ldg(ptr);
                ptr += 2 * HWSZ;
                float o = __shfl_xor_sync(FULL, v, 16);
                if (lane < 16) {
                    __nv_bfloat162 t2 = __floats2bfloat162_rn(v, o);
                    *(uint32_t*)(sm8 + (xb - sb) + (((uint32_t)(4 * it)) ^ sx)) = *(uint32_t*)&t2;
                }
            }
            __syncwarp();
        }

        // ---- GEMM1: h = x . W1^T  (128 mma) ----
        float acc1[8][4];
        #pragma unroll
        for (int t = 0; t < 8; t++) { acc1[t][0]=0.f; acc1[t][1]=0.f; acc1[t][2]=0.f; acc1[t][3]=0.f; }
        #pragma unroll
        for (int kk = 0; kk < 16; kk++) {
            uint32_t a[4];
            ldm4(a, aX + (((kk * 32) | c16) ^ swA));
            #pragma unroll
            for (int np = 0; np < 4; np++) {
                uint32_t b[4];
                ldm4(b, bW1 + np * 8192 + (((kk * 32) | cB16) ^ swB));
                mma16816(acc1[2*np],   a, b);
                mma16816(acc1[2*np+1], a, b + 2);
            }
        }
        // epi1: bias + relu -> h smem
        {
            const uint32_t h1 = sb + S_H + gr1 * 128, h2 = sb + S_H + gr2 * 128;
            #pragma unroll
            for (int t = 0; t < 8; t++) {
                int col = t * 8 + e;
                float2 bb = *(float2*)&sB1[col];
                float v0 = fmaxf(acc1[t][0] + bb.x, 0.f), v1 = fmaxf(acc1[t][1] + bb.y, 0.f);
                float v2 = fmaxf(acc1[t][2] + bb.x, 0.f), v3 = fmaxf(acc1[t][3] + bb.y, 0.f);
                __nv_bfloat162 p01 = __floats2bfloat162_rn(v0, v1);
                __nv_bfloat162 p23 = __floats2bfloat162_rn(v2, v3);
                uint32_t off = ((uint32_t)(col * 2)) ^ swc;
                *(uint32_t*)(sm8 + (h1 - sb) + off) = *(uint32_t*)&p01;
                *(uint32_t*)(sm8 + (h2 - sb) + off) = *(uint32_t*)&p23;
            }
            __syncwarp();
        }

        // ---- GEMM2: f_pre = h . W2^T  (32 mma) ----
        float acc2[8][4];
        #pragma unroll
        for (int t = 0; t < 8; t++) { acc2[t][0]=0.f; acc2[t][1]=0.f; acc2[t][2]=0.f; acc2[t][3]=0.f; }
        #pragma unroll
        for (int kk = 0; kk < 4; kk++) {
            uint32_t a[4];
            ldm4(a, aH + (((kk * 32) | c16) ^ swA));
            #pragma unroll
            for (int np = 0; np < 4; np++) {
                uint32_t b[4];
                ldm4(b, bW2 + np * 2048 + (((kk * 32) | cB16) ^ swB));
                mma16816(acc2[2*np],   a, b);
                mma16816(acc2[2*np+1], a, b + 2);
            }
        }
        // epi2: sigmoid, sum f^2 (fp32), hi/lo split -> smem
        {
            const uint32_t fh1 = sb + S_FH + gr1 * 128, fh2 = sb + S_FH + gr2 * 128;
            const uint32_t fl1 = sb + S_FL + gr1 * 128, fl2 = sb + S_FL + gr2 * 128;
            float s2a = 0.f, s2b = 0.f;
            #pragma unroll
            for (int t = 0; t < 8; t++) {
                int col = t * 8 + e;
                float2 bb = *(float2*)&sB2[col];
                float v0 = sigmoidf_(acc2[t][0] + bb.x), v1 = sigmoidf_(acc2[t][1] + bb.y);
                float v2 = sigmoidf_(acc2[t][2] + bb.x), v3 = sigmoidf_(acc2[t][3] + bb.y);
                s2a = fmaf(v0, v0, s2a); s2a = fmaf(v1, v1, s2a);
                s2b = fmaf(v2, v2, s2b); s2b = fmaf(v3, v3, s2b);
                __nv_bfloat16 h0 = __float2bfloat16(v0), h1b = __float2bfloat16(v1);
                __nv_bfloat16 h2b = __float2bfloat16(v2), h3 = __float2bfloat16(v3);
                __nv_bfloat16 l0 = __float2bfloat16(v0 - __bfloat162float(h0));
                __nv_bfloat16 l1 = __float2bfloat16(v1 - __bfloat162float(h1b));
                __nv_bfloat16 l2 = __float2bfloat16(v2 - __bfloat162float(h2b));
                __nv_bfloat16 l3 = __float2bfloat16(v3 - __bfloat162float(h3));
                uint32_t off = ((uint32_t)(col * 2)) ^ swc;
                __nv_bfloat162 t01 = __halves2bfloat162(h0, h1b), t23 = __halves2bfloat162(h2b, h3);
                __nv_bfloat162 u01 = __halves2bfloat162(l0, l1),  u23 = __halves2bfloat162(l2, l3);
                *(uint32_t*)(sm8 + (fh1 - sb) + off) = *(uint32_t*)&t01;
                *(uint32_t*)(sm8 + (fh2 - sb) + off) = *(uint32_t*)&t23;
                *(uint32_t*)(sm8 + (fl1 - sb) + off) = *(uint32_t*)&u01;
                *(uint32_t*)(sm8 + (fl2 - sb) + off) = *(uint32_t*)&u23;
            }
            s2a += __shfl_xor_sync(FULL, s2a, 1); s2a += __shfl_xor_sync(FULL, s2a, 2);
            s2b += __shfl_xor_sync(FULL, s2b, 1); s2b += __shfl_xor_sync(FULL, s2b, 2);
            if ((lane & 3) == 0) { sS2[gr1] = s2a; sS2[gr2] = s2b; }
            __syncwarp();
        }

        // ---- GEMM3: dot' = -2 f.p via hi/lo split (312 mma) ----
        float acc3[26][4];
        #pragma unroll
        for (int t = 0; t < 26; t++) { acc3[t][0]=0.f; acc3[t][1]=0.f; acc3[t][2]=0.f; acc3[t][3]=0.f; }
        #pragma unroll
        for (int kk = 0; kk < 4; kk++) {
            uint32_t ah[4], al[4];
            uint32_t ka = ((kk * 32) | c16) ^ swA;
            ldm4(ah, aFH + ka);
            ldm4(al, aFL + ka);
            uint32_t kb = ((kk * 32) | cB16) ^ swB;
            #pragma unroll
            for (int np = 0; np < 13; np++) {
                uint32_t bh[4], bl[4];
                ldm4(bh, bPH + np * 2048 + kb);
                ldm4(bl, bPL + np * 2048 + kb);
                float* c0 = acc3[2*np];
                float* c1 = acc3[2*np+1];
                mma16816(c0, ah, bh);     mma16816(c1, ah, bh + 2);
                mma16816(c0, ah, bl);     mma16816(c1, ah, bl + 2);
                mma16816(c0, al, bh);     mma16816(c1, al, bh + 2);
            }
        }

        // ---- epi3: distance + spatial min ----
        {
            const bool A1 = gr1 - w * 0 + 0 + (0) < 0 ? false : ((w * 16 + r1) < bndw);
            const bool A2 = ((w * 16 + r1 + 8) < bndw);
            const float s2r1 = sS2[gr1], s2r2 = sS2[gr2];
            float* wA = sWA + w * NPP;
            float* wB = sWB + w * NPP;
            #pragma unroll
            for (int t = 0; t < 26; t++) {
                int col = t * 8 + e;
                float2 pp = *(float2*)&sP2[col];
                float d0 = fmaxf(acc3[t][0] + s2r1 + pp.x, 0.f);
                float d1 = fmaxf(acc3[t][1] + s2r1 + pp.y, 0.f);
                float d2 = fmaxf(acc3[t][2] + s2r2 + pp.x, 0.f);
                float d3 = fmaxf(acc3[t][3] + s2r2 + pp.y, 0.f);
                float a0 = fminf(A1 ? d0 : INF, A2 ? d2 : INF);
                float a1 = fminf(A1 ? d1 : INF, A2 ? d3 : INF);
                a0 = wmin3(a0); a1 = wmin3(a1);
                if (lane < 4) *(float2*)&wA[col] = make_float2(a0, a1);
                if (hasB) {
                    float b0 = fminf(A1 ? INF : d0, A2 ? INF : d2);
                    float b1v = fminf(A1 ? INF : d1, A2 ? INF : d3);
                    b0 = wmin3(b0); b1v = wmin3(b1v);
                    if (lane < 4) *(float2*)&wB[col] = make_float2(b0, b1v);
                }
            }
        }
        __syncthreads();
        if (tid < NPP) {
            float m = INF;
            #pragma unroll
            for (int ww = 0; ww < 8; ww++) m = fminf(m, sWA[ww * NPP + tid]);
            if (tid < NP) atomicMin(gmin + (size_t)nA * NP + tid, __float_as_uint(m));
            if (hasB) {
                float mb = INF;
                #pragma unroll
                for (int ww = 0; ww < 8; ww++) mb = fminf(mb, sWB[ww * NPP + tid]);
                if (tid < NP) atomicMin(gmin + (size_t)(nA + 1) * NP + tid, __float_as_uint(mb));
            }
        }
        __syncthreads();
    }
}

__global__ void init_min(unsigned* __restrict__ gmin) {
    int i = blockIdx.x * blockDim.x + threadIdx.x;
    if (i < NIMG * NP) gmin[i] = 0x7F800000u;
}

__global__ void logits_k(const float* __restrict__ md, const float* __restrict__ lw,
                         const float* __restrict__ lb, float* __restrict__ out) {
    int n    = blockIdx.x;
    int cls  = threadIdx.x >> 5;
    int lane = threadIdx.x & 31;
    if (cls >= NCLS) return;
    float s = 0.f;
    for (int p = lane; p < NP; p += 32)
        s = fmaf(-md[n * NP + p], lw[cls * NP + p], s);
    #pragma unroll
    for (int sh = 16; sh > 0; sh >>= 1)
        s += __shfl_xor_sync(FULL, s, sh);
    if (lane == 0) out[n * NCLS + cls] = s + lb[cls];
}

extern "C" void kernel_launch(void* const* d_in, const int* in_sizes, int n_in,
                              void* d_out, int out_size)
{
    const float* x    = (const float*)d_in[0];
    const float* W1   = (const float*)d_in[1];
    const float* b1   = (const float*)d_in[2];
    const float* W2   = (const float*)d_in[3];
    const float* b2   = (const float*)d_in[4];
    const float* prot = (const float*)d_in[5];
    const float* lw   = (const float*)d_in[6];
    const float* lb   = (const float*)d_in[7];

    float* out     = (float*)d_out;
    float* logits  = out;                            // [256, 10]
    unsigned* gmin = (unsigned*)(out + NIMG * NCLS); // [256, 200] float bits

    cudaFuncSetAttribute(proto_mma, cudaFuncAttributeMaxDynamicSharedMemorySize, SMEM_TOTAL);
    int sms = 148;
    cudaDeviceGetAttribute(&sms, cudaDevAttrMultiProcessorCount, 0);

    init_min<<<(NIMG * NP + 255) / 256, 256>>>(gmin);
    proto_mma<<<sms, TPB, SMEM_TOTAL>>>(x, W1, b1, W2, b2, prot, gmin);
    logits_k<<<NIMG, NCLS * 32>>>((const float*)gmin, lw, lb, logits);
}

// round 9
// speedup vs baseline: 3.9476x; 2.2449x over previous
#include <cuda_runtime.h>
#include <cuda_fp16.h>
#include <cstdint>

#define NP     200
#define NPP    208
#define NCLS   10
#define NIMG   256
#define HWSZ   784
#define CIN    256
#define DD     64
#define MT     128
#define NTILES 1568         // 200704 / 128
#define TPB    256
#define FULL   0xffffffffu

// ---- smem byte offsets ----
#define S_X    0            // x tile [256 c][128 px] fp16, 256 B/row = 65536
#define S_W1   65536        // [64 o][256 c] fp16, 512 B/row          = 32768
#define S_H    98304        // [128 px][64] fp16, 128 B/row           = 16384
#define S_F    114688       // f [128][64] fp16                       = 16384
#define S_W2   131072       // [64][64] fp16                          = 8192
#define S_P    139264       // -2*prot [208][64] fp16                 = 26624
#define S_P2   165888       // [208] f32
#define S_B1   166784
#define S_B2   167040
#define S_S2   167296       // [128] f32
#define S_WA   167808       // [8][208] f32 = 6656
#define S_WB   174464
#define SMEM_TOTAL 181120

__device__ float g_part[NTILES * 2 * NPP];   // per-tile partial mins (slot0: image nA, slot1: nA+1)

__device__ __forceinline__ uint32_t smem_u32(const void* p) {
    uint32_t a;
    asm("{ .reg .u64 t; cvta.to.shared.u64 t, %1; cvt.u32.u64 %0, t; }" : "=r"(a) : "l"(p));
    return a;
}
__device__ __forceinline__ void ldm4(uint32_t* r, uint32_t addr) {
    asm volatile("ldmatrix.sync.aligned.m8n8.x4.shared.b16 {%0,%1,%2,%3}, [%4];"
        : "=r"(r[0]), "=r"(r[1]), "=r"(r[2]), "=r"(r[3]) : "r"(addr));
}
__device__ __forceinline__ void ldm4t(uint32_t* r, uint32_t addr) {
    asm volatile("ldmatrix.sync.aligned.m8n8.x4.trans.shared.b16 {%0,%1,%2,%3}, [%4];"
        : "=r"(r[0]), "=r"(r[1]), "=r"(r[2]), "=r"(r[3]) : "r"(addr));
}
__device__ __forceinline__ void mma16816(float* c, const uint32_t* a, const uint32_t* b) {
    asm volatile("mma.sync.aligned.m16n8k16.row.col.f32.f16.f16.f32 "
        "{%0,%1,%2,%3}, {%4,%5,%6,%7}, {%8,%9}, {%0,%1,%2,%3};"
        : "+f"(c[0]), "+f"(c[1]), "+f"(c[2]), "+f"(c[3])
        : "r"(a[0]), "r"(a[1]), "r"(a[2]), "r"(a[3]), "r"(b[0]), "r"(b[1]));
}
__device__ __forceinline__ uint32_t swz(int row, int cb, int rowb) {
    return (uint32_t)(row * rowb) + (uint32_t)(cb ^ ((row & 7) << 4));
}
__device__ __forceinline__ float sigmoidf_(float v) {
    return __fdividef(1.f, 1.f + __expf(-v));
}
__device__ __forceinline__ float wmin3(float m) {
    m = fminf(m, __shfl_xor_sync(FULL, m, 4));
    m = fminf(m, __shfl_xor_sync(FULL, m, 8));
    m = fminf(m, __shfl_xor_sync(FULL, m, 16));
    return m;
}

__global__ __launch_bounds__(TPB, 1)
void proto_mma(const float* __restrict__ x, const float* __restrict__ W1,
               const float* __restrict__ b1, const float* __restrict__ W2,
               const float* __restrict__ b2, const float* __restrict__ prot)
{
    extern __shared__ char sm8[];
    const uint32_t sb = smem_u32(sm8);
    float* sP2 = (float*)(sm8 + S_P2);
    float* sB1 = (float*)(sm8 + S_B1);
    float* sB2 = (float*)(sm8 + S_B2);
    float* sS2 = (float*)(sm8 + S_S2);
    float* sWA = (float*)(sm8 + S_WA);
    float* sWB = (float*)(sm8 + S_WB);

    const int tid  = threadIdx.x;
    const int w    = tid >> 5;
    const int lane = tid & 31;

    // ---- one-time weight staging (fp16, swizzled) ----
    for (int i = tid; i < DD * CIN; i += TPB) {
        int o = i >> 8, c = i & 255;
        *(__half*)(sm8 + S_W1 + swz(o, c * 2, 512)) = __float2half(W1[i]);
    }
    for (int i = tid; i < DD * DD; i += TPB) {
        int o = i >> 6, k = i & 63;
        *(__half*)(sm8 + S_W2 + swz(o, k * 2, 128)) = __float2half(W2[i]);
    }
    for (int i = tid; i < NPP * DD; i += TPB) {
        int p = i >> 6, c = i & 63;
        float v = (p < NP) ? (-2.0f * prot[p * DD + c]) : 0.0f;
        *(__half*)(sm8 + S_P + swz(p, c * 2, 128)) = __float2half(v);
    }
    if (tid < NPP) {
        float s = 0.f;
        if (tid < NP) {
            #pragma unroll
            for (int c = 0; c < DD; c++) { float v = prot[tid * DD + c]; s = fmaf(v, v, s); }
        }
        sP2[tid] = s;
    }
    if (tid < DD) { sB1[tid] = b1[tid]; sB2[tid] = b2[tid]; }
    __syncthreads();

    // ---- per-thread fragment geometry ----
    const int l7   = lane & 7;
    const int rowA = w * 16 + (lane & 15);           // A row (non-trans, H/F tiles)
    const int c16  = lane & 16;
    const int swA  = (rowA & 7) << 4;
    const int rowB = (lane & 7) | ((lane & 16) >> 1);
    const int cB16 = (lane & 8) << 1;
    const int swB  = (rowB & 7) << 4;
    const int r1 = lane >> 2, e = (lane & 3) * 2;
    const int gr1 = w * 16 + r1, gr2 = gr1 + 8;
    const int swc = (r1 & 7) << 4;

    // trans-A base for X tile [c][px]: k-rows via lanes, px cols via lane&8
    const uint32_t aX  = sb + S_X + (uint32_t)((l7 + ((lane & 16) >> 1)) << 8)
                       + (uint32_t)(((w << 5) + ((lane & 8) << 1)) ^ (l7 << 4));
    const uint32_t aH  = sb + S_H + rowA * 128;
    const uint32_t aF  = sb + S_F + rowA * 128;
    const uint32_t bW1 = sb + S_W1 + rowB * 512;
    const uint32_t bW2 = sb + S_W2 + rowB * 128;
    const uint32_t bP  = sb + S_P  + rowB * 128;
    const float INF = __int_as_float(0x7f800000);

    for (int tile = blockIdx.x; tile < NTILES; tile += gridDim.x) {
        const int px0  = tile * MT;
        const int nA   = px0 / HWSZ;
        const int bndg = (nA + 1) * HWSZ;
        const bool hasB = (px0 + MT - 1) >= bndg;
        const int bndw = bndg - px0;

        // ---- stage x -> [c][px] fp16 smem (coalesced float4 loads) ----
        {
            const int g4   = px0 + (lane << 2);
            const int n4   = g4 / HWSZ;
            const int pix4 = g4 - n4 * HWSZ;
            const float* bpx = x + ((size_t)n4 * CIN) * HWSZ + pix4;
            #pragma unroll 8
            for (int i = 0; i < 32; i++) {
                const int c = (w << 5) + i;
                const float4 v = *(const float4*)(bpx + (size_t)c * HWSZ);
                __half2 p0 = __floats2half2_rn(v.x, v.y);
                __half2 p1 = __floats2half2_rn(v.z, v.w);
                uint32_t off = ((uint32_t)c << 8) + (uint32_t)((lane << 3) ^ ((c & 7) << 4));
                uint2 st;
                st.x = *(uint32_t*)&p0; st.y = *(uint32_t*)&p1;
                *(uint2*)(sm8 + S_X + off) = st;
            }
        }
        __syncthreads();

        // ---- GEMM1: h = x . W1^T  (128 mma, A via ldmatrix.trans) ----
        float acc1[8][4];
        #pragma unroll
        for (int t = 0; t < 8; t++) { acc1[t][0]=0.f; acc1[t][1]=0.f; acc1[t][2]=0.f; acc1[t][3]=0.f; }
        #pragma unroll
        for (int kk = 0; kk < 16; kk++) {
            uint32_t a[4];
            ldm4t(a, aX + kk * 4096);
            #pragma unroll
            for (int np = 0; np < 4; np++) {
                uint32_t b[4];
                ldm4(b, bW1 + np * 8192 + (((kk * 32) | cB16) ^ swB));
                mma16816(acc1[2*np],   a, b);
                mma16816(acc1[2*np+1], a, b + 2);
            }
        }
        // epi1: bias + relu -> h smem
        {
            const uint32_t h1 = sb + S_H + gr1 * 128, h2 = sb + S_H + gr2 * 128;
            #pragma unroll
            for (int t = 0; t < 8; t++) {
                int col = t * 8 + e;
                float2 bb = *(float2*)&sB1[col];
                float v0 = fmaxf(acc1[t][0] + bb.x, 0.f), v1 = fmaxf(acc1[t][1] + bb.y, 0.f);
                float v2 = fmaxf(acc1[t][2] + bb.x, 0.f), v3 = fmaxf(acc1[t][3] + bb.y, 0.f);
                __half2 p01 = __floats2half2_rn(v0, v1);
                __half2 p23 = __floats2half2_rn(v2, v3);
                uint32_t off = ((uint32_t)(col * 2)) ^ swc;
                *(uint32_t*)(sm8 + (h1 - sb) + off) = *(uint32_t*)&p01;
                *(uint32_t*)(sm8 + (h2 - sb) + off) = *(uint32_t*)&p23;
            }
            __syncwarp();
        }

        // ---- GEMM2: f_pre = h . W2^T  (32 mma) ----
        float acc2[8][4];
        #pragma unroll
        for (int t = 0; t < 8; t++) { acc2[t][0]=0.f; acc2[t][1]=0.f; acc2[t][2]=0.f; acc2[t][3]=0.f; }
        #pragma unroll
        for (int kk = 0; kk < 4; kk++) {
            uint32_t a[4];
            ldm4(a, aH + (((kk * 32) | c16) ^ swA));
            #pragma unroll
            for (int np = 0; np < 4; np++) {
                uint32_t b[4];
                ldm4(b, bW2 + np * 2048 + (((kk * 32) | cB16) ^ swB));
                mma16816(acc2[2*np],   a, b);
                mma16816(acc2[2*np+1], a, b + 2);
            }
        }
        // epi2: sigmoid, fp32 sum f^2, fp16 f -> smem
        {
            const uint32_t f1 = sb + S_F + gr1 * 128, f2 = sb + S_F + gr2 * 128;
            float s2a = 0.f, s2b = 0.f;
            #pragma unroll
            for (int t = 0; t < 8; t++) {
                int col = t * 8 + e;
                float2 bb = *(float2*)&sB2[col];
                float v0 = sigmoidf_(acc2[t][0] + bb.x), v1 = sigmoidf_(acc2[t][1] + bb.y);
                float v2 = sigmoidf_(acc2[t][2] + bb.x), v3 = sigmoidf_(acc2[t][3] + bb.y);
                s2a = fmaf(v0, v0, s2a); s2a = fmaf(v1, v1, s2a);
                s2b = fmaf(v2, v2, s2b); s2b = fmaf(v3, v3, s2b);
                __half2 t01 = __floats2half2_rn(v0, v1);
                __half2 t23 = __floats2half2_rn(v2, v3);
                uint32_t off = ((uint32_t)(col * 2)) ^ swc;
                *(uint32_t*)(sm8 + (f1 - sb) + off) = *(uint32_t*)&t01;
                *(uint32_t*)(sm8 + (f2 - sb) + off) = *(uint32_t*)&t23;
            }
            s2a += __shfl_xor_sync(FULL, s2a, 1); s2a += __shfl_xor_sync(FULL, s2a, 2);
            s2b += __shfl_xor_sync(FULL, s2b, 1); s2b += __shfl_xor_sync(FULL, s2b, 2);
            if ((lane & 3) == 0) { sS2[gr1] = s2a; sS2[gr2] = s2b; }
            __syncwarp();
        }

        // ---- GEMM3: dot' = -2 f.p  (104 mma) ----
        float acc3[26][4];
        #pragma unroll
        for (int t = 0; t < 26; t++) { acc3[t][0]=0.f; acc3[t][1]=0.f; acc3[t][2]=0.f; acc3[t][3]=0.f; }
        #pragma unroll
        for (int kk = 0; kk < 4; kk++) {
            uint32_t a[4];
            ldm4(a, aF + (((kk * 32) | c16) ^ swA));
            uint32_t kb = ((kk * 32) | cB16) ^ swB;
            #pragma unroll
            for (int np = 0; np < 13; np++) {
                uint32_t b[4];
                ldm4(b, bP + np * 2048 + kb);
                mma16816(acc3[2*np],   a, b);
                mma16816(acc3[2*np+1], a, b + 2);
            }
        }

        // ---- epi3: distance + spatial min ----
        {
            const bool A1 = (w * 16 + r1)     < bndw;
            const bool A2 = (w * 16 + r1 + 8) < bndw;
            const float s2r1 = sS2[gr1], s2r2 = sS2[gr2];
            float* wA = sWA + w * NPP;
            float* wB = sWB + w * NPP;
            #pragma unroll
            for (int t = 0; t < 26; t++) {
                int col = t * 8 + e;
                float2 pp = *(float2*)&sP2[col];
                float d0 = fmaxf(acc3[t][0] + s2r1 + pp.x, 0.f);
                float d1 = fmaxf(acc3[t][1] + s2r1 + pp.y, 0.f);
                float d2 = fmaxf(acc3[t][2] + s2r2 + pp.x, 0.f);
                float d3 = fmaxf(acc3[t][3] + s2r2 + pp.y, 0.f);
                float a0 = fminf(A1 ? d0 : INF, A2 ? d2 : INF);
                float a1 = fminf(A1 ? d1 : INF, A2 ? d3 : INF);
                a0 = wmin3(a0); a1 = wmin3(a1);
                if (lane < 4) *(float2*)&wA[col] = make_float2(a0, a1);
                if (hasB) {
                    float b0 = fminf(A1 ? INF : d0, A2 ? INF : d2);
                    float b1v = fminf(A1 ? INF : d1, A2 ? INF : d3);
                    b0 = wmin3(b0); b1v = wmin3(b1v);
                    if (lane < 4) *(float2*)&wB[col] = make_float2(b0, b1v);
                }
            }
        }
        __syncthreads();
        if (tid < NPP) {
            float m = INF;
            #pragma unroll
            for (int ww = 0; ww < 8; ww++) m = fminf(m, sWA[ww * NPP + tid]);
            g_part[(size_t)(tile * 2) * NPP + tid] = m;
            float mb = INF;
            if (hasB) {
                #pragma unroll
                for (int ww = 0; ww < 8; ww++) mb = fminf(mb, sWB[ww * NPP + tid]);
            }
            g_part[(size_t)(tile * 2 + 1) * NPP + tid] = mb;
        }
        __syncthreads();
    }
}

// final: per-image min over tile partials + logits
__global__ void reduce_k(const float* __restrict__ lw, const float* __restrict__ lb,
                         float* __restrict__ logits, float* __restrict__ md)
{
    __shared__ float sm[NPP];
    const int n = blockIdx.x;
    const int tid = threadIdx.x;
    const float INF = __int_as_float(0x7f800000);

    if (tid < NPP) {
        int t0 = (n * HWSZ) >> 7;
        int t1 = (n * HWSZ + HWSZ - 1) >> 7;
        float m = INF;
        for (int t = t0; t <= t1; t++) {
            int nAt = (t * MT) / HWSZ;
            int slot = (nAt == n) ? 0 : 1;
            m = fminf(m, g_part[(size_t)(t * 2 + slot) * NPP + tid]);
        }
        sm[tid] = m;
        if (tid < NP) md[n * NP + tid] = m;
    }
    __syncthreads();

    const int w = tid >> 5, lane = tid & 31;
    for (int cls = w; cls < NCLS; cls += 8) {
        float s = 0.f;
        for (int p = lane; p < NP; p += 32)
            s = fmaf(-sm[p], lw[cls * NP + p], s);
        #pragma unroll
        for (int sh = 16; sh > 0; sh >>= 1)
            s += __shfl_xor_sync(FULL, s, sh);
        if (lane == 0) logits[n * NCLS + cls] = s + lb[cls];
    }
}

extern "C" void kernel_launch(void* const* d_in, const int* in_sizes, int n_in,
                              void* d_out, int out_size)
{
    const float* x    = (const float*)d_in[0];
    const float* W1   = (const float*)d_in[1];
    const float* b1   = (const float*)d_in[2];
    const float* W2   = (const float*)d_in[3];
    const float* b2   = (const float*)d_in[4];
    const float* prot = (const float*)d_in[5];
    const float* lw   = (const float*)d_in[6];
    const float* lb   = (const float*)d_in[7];

    float* out    = (float*)d_out;
    float* logits = out;                       // [256, 10]
    float* md     = out + NIMG * NCLS;         // [256, 200]

    cudaFuncSetAttribute(proto_mma, cudaFuncAttributeMaxDynamicSharedMemorySize, SMEM_TOTAL);
    int sms = 148;
    cudaDeviceGetAttribute(&sms, cudaDevAttrMultiProcessorCount, 0);

    proto_mma<<<sms, TPB, SMEM_TOTAL>>>(x, W1, b1, W2, b2, prot);
    reduce_k<<<NIMG, TPB>>>(lw, lb, logits, md);
}